// round 16
// baseline (speedup 1.0000x reference)
#include <cuda_runtime.h>
#include <cstdint>
#include <cstddef>

// Problem constants
#define B_    32
#define S_    577          // 24*24 + 1
#define E_    768
#define H_    12
#define DH_   64
#define PT_   24
#define QKV3_ 2304         // 3*E
#define NROT_ 576          // S-1 rope positions
#define BH_   (B_ * H_)    // 384

// Scratch (device globals; allocation-free per harness rules)
__device__ float g_ctx[(size_t)B_ * S_ * E_];      // [b*s, h*d] (tf32-rounded)
__device__ float g_q[(size_t)BH_ * S_ * DH_];      // [b,h,s,d] (tf32-rounded)
__device__ float g_k[(size_t)BH_ * S_ * DH_];
__device__ float g_v[(size_t)BH_ * S_ * DH_];
__device__ float g_xr[(size_t)B_ * S_ * E_];       // x rounded to tf32
__device__ float g_w1t[(size_t)QKV3_ * E_];        // W_qkv rounded + transposed [N][K]
__device__ float g_w2t[(size_t)E_ * E_];           // W_proj rounded + transposed [N][K]
__device__ float g_cos[NROT_ * DH_];
__device__ float g_sin[NROT_ * DH_];

// ---------------------------------------------------------------------------
// RoPE table
// ---------------------------------------------------------------------------
__global__ void rope_build_kernel() {
    int p = blockIdx.x;      // 0..575
    int d = threadIdx.x;     // 0..63
    int r = p / PT_, c = p % PT_;
    int tcoord = (d < 32) ? r : c;
    int dd = (d < 32) ? d : d - 32;
    int fi = dd >> 1;        // freq index 0..15
    float inv = powf(10000.0f, -(float)(2 * fi) / 32.0f);
    float ang = (float)tcoord * inv;
    g_cos[p * DH_ + d] = cosf(ang);
    g_sin[p * DH_ + d] = sinf(ang);
}

// ---------------------------------------------------------------------------
// tf32 helpers
// ---------------------------------------------------------------------------
__device__ __forceinline__ uint32_t f2tf32(float x) {
    uint32_t r;
    asm("cvt.rna.tf32.f32 %0, %1;" : "=r"(r) : "f"(x));
    return r;
}

#define MMA_TF32(d, a, b)                                                  \
    asm volatile(                                                          \
        "mma.sync.aligned.m16n8k8.row.col.f32.tf32.tf32.f32 "              \
        "{%0,%1,%2,%3}, {%4,%5,%6,%7}, {%8,%9}, {%0,%1,%2,%3};"            \
        : "+f"(d[0]), "+f"(d[1]), "+f"(d[2]), "+f"(d[3])                   \
        : "r"(a[0]), "r"(a[1]), "r"(a[2]), "r"(a[3]), "r"(b[0]), "r"(b[1]))

#define LDSM_X4(r0, r1, r2, r3, addr)                                      \
    asm volatile(                                                          \
        "ldmatrix.sync.aligned.m8n8.x4.shared.b16 {%0,%1,%2,%3}, [%4];"    \
        : "=r"(r0), "=r"(r1), "=r"(r2), "=r"(r3) : "r"(addr))

__device__ __forceinline__ void cp16(uint32_t dst, const void* src, bool pred) {
    asm volatile("cp.async.cg.shared.global [%0], [%1], 16, %2;"
                 :: "r"(dst), "l"(src), "r"(pred ? 16 : 0));
}

// ---------------------------------------------------------------------------
// Elementwise round-to-tf32 (rna). n4 = element count / 4. (for x)
// ---------------------------------------------------------------------------
__global__ void round_tf32_kernel(const float* __restrict__ in,
                                  float* __restrict__ out, int n4) {
    int i = blockIdx.x * blockDim.x + threadIdx.x;
    if (i < n4) {
        float4 v = ((const float4*)in)[i];
        uint4 u = make_uint4(f2tf32(v.x), f2tf32(v.y), f2tf32(v.z), f2tf32(v.w));
        ((uint4*)out)[i] = u;
    }
}

// ---------------------------------------------------------------------------
// Round-to-tf32 + transpose: in [K][N] -> out [N][K]. 32x32 tiles.
// grid (N/32, K/32), block (32, 8).
// ---------------------------------------------------------------------------
__global__ void round_t_kernel(const float* __restrict__ in,
                               float* __restrict__ out, int K, int N) {
    __shared__ float tile[32][33];
    int nb = blockIdx.x * 32, kb = blockIdx.y * 32;
    int tx = threadIdx.x, ty = threadIdx.y;
    #pragma unroll
    for (int j = 0; j < 32; j += 8)
        tile[ty + j][tx] = in[(size_t)(kb + ty + j) * N + nb + tx];
    __syncthreads();
    #pragma unroll
    for (int j = 0; j < 32; j += 8)
        out[(size_t)(nb + ty + j) * K + kb + tx] =
            __uint_as_float(f2tf32(tile[tx][ty + j]));
}

// ---------------------------------------------------------------------------
// TF32 GEMM mainloop. CTA tile 128x256, BK=64, 2-stage cp.async double
// buffer. 8 warps (2m x 4n), warp 64x64. ALL fragment loads via ldmatrix.
// LDSM x4 matrix order = addressing-lane order: m0 (lanes 0-7), m1 (8-15),
// m2 (16-23), m3 (24-31). With the A-like fragoff: m0/m1 = rows 0-7/8-15
// at col k; m2/m3 = same rows at col k+4.
// ---------------------------------------------------------------------------
#define TBM 128
#define TBN 256
#define TBK 64
#define TSTRIDE (TBK + 4)   // 68 words per smem row
#define STAGES 2

struct GemmCtx {
    int wm, wn, g, t, lane, m0, n0;
};

__device__ __forceinline__ void gemm_mainloop(
    const float* __restrict__ A, const float* __restrict__ Bt,
    int M, int N, int K, const GemmCtx& cx,
    uint32_t (*As)[TBM][TSTRIDE], uint32_t (*Bs)[TBN][TSTRIDE],
    float acc[4][8][4])
{
    const int tid = threadIdx.x;

    auto load_stage = [&](int s, int k0) {
        #pragma unroll
        for (int i = 0; i < 8; i++) {
            int c = tid + i * 256;           // 2048 A chunks (128 rows x 16 quads)
            int row = c >> 4, quad = c & 15;
            int gr = cx.m0 + row;
            uint32_t dst = (uint32_t)__cvta_generic_to_shared(&As[s][row][quad * 4]);
            cp16(dst, A + (size_t)gr * K + k0 + quad * 4, gr < M);
        }
        #pragma unroll
        for (int i = 0; i < 16; i++) {
            int c = tid + i * 256;           // 4096 B chunks (256 n-rows x 16 quads)
            int row = c >> 4, quad = c & 15;
            uint32_t dst = (uint32_t)__cvta_generic_to_shared(&Bs[s][row][quad * 4]);
            cp16(dst, Bt + (size_t)(cx.n0 + row) * K + k0 + quad * 4, true);
        }
        asm volatile("cp.async.commit_group;");
    };

    #pragma unroll
    for (int mt = 0; mt < 4; mt++)
        #pragma unroll
        for (int nt = 0; nt < 8; nt++)
            #pragma unroll
            for (int i = 0; i < 4; i++) acc[mt][nt][i] = 0.0f;

    const int NKT = K / TBK;   // 12

    // Lane-dependent LDSM byte offset (A-like pattern for both A and B):
    // lanes 0-15 -> rows 0-15 at col 0; lanes 16-31 -> rows 0-15 at col +4.
    const int lane = cx.lane;
    const uint32_t fragoff =
        ((uint32_t)((lane & 15) * TSTRIDE + ((lane >> 4) << 2))) * 4;

    load_stage(0, 0);

    for (int kt = 0; kt < NKT; kt++) {
        __syncthreads();
        if (kt + 1 < NKT) {
            load_stage((kt + 1) & 1, (kt + 1) * TBK);
            asm volatile("cp.async.wait_group 1;");
        } else {
            asm volatile("cp.async.wait_group 0;");
        }
        __syncthreads();

        int cur = kt & 1;
        uint32_t asb = (uint32_t)__cvta_generic_to_shared(&As[cur][0][0]);
        uint32_t bsb = (uint32_t)__cvta_generic_to_shared(&Bs[cur][0][0]);

        #pragma unroll
        for (int ks = 0; ks < 8; ks++) {
            int k = ks * 8;
            uint32_t af[4][4], bf[8][2];
            #pragma unroll
            for (int mt = 0; mt < 4; mt++) {
                int rm = cx.wm + mt * 16;
                uint32_t a = asb + (uint32_t)((rm * TSTRIDE + k) * 4) + fragoff;
                // m0=(g,t), m1=(g+8,t), m2=(g,t+4), m3=(g+8,t+4) == A frag order
                LDSM_X4(af[mt][0], af[mt][1], af[mt][2], af[mt][3], a);
            }
            #pragma unroll
            for (int p = 0; p < 4; p++) {
                int cn = cx.wn + p * 16;
                uint32_t a = bsb + (uint32_t)((cn * TSTRIDE + k) * 4) + fragoff;
                // m0 = n rows cn..+7 @k  -> bf[2p][0]
                // m1 = n rows cn+8..+15 @k -> bf[2p+1][0]
                // m2 = n rows cn..+7 @k+4 -> bf[2p][1]
                // m3 = n rows cn+8..+15 @k+4 -> bf[2p+1][1]
                LDSM_X4(bf[2 * p][0], bf[2 * p + 1][0],
                        bf[2 * p][1], bf[2 * p + 1][1], a);
            }
            #pragma unroll
            for (int mt = 0; mt < 4; mt++)
                #pragma unroll
                for (int nt = 0; nt < 8; nt++)
                    MMA_TF32(acc[mt][nt], af[mt], bf[nt]);
        }
    }
}

// ---------------------------------------------------------------------------
// Generic tf32 GEMM + bias (used for proj). B pre-transposed [N][K].
// ---------------------------------------------------------------------------
__global__ __launch_bounds__(256, 1)
void gemm_tf32_kernel(const float* __restrict__ A,
                      const float* __restrict__ Bt,
                      const float* __restrict__ bias,
                      float* __restrict__ C,
                      int M, int N, int K) {
    __shared__ uint32_t As[STAGES][TBM][TSTRIDE];
    __shared__ uint32_t Bs[STAGES][TBN][TSTRIDE];

    const int tid  = threadIdx.x;
    const int lane = tid & 31;
    const int warp = tid >> 5;
    GemmCtx cx;
    cx.wm = (warp & 1) * 64;
    cx.wn = (warp >> 1) * 64;
    cx.g = lane >> 2;
    cx.t = lane & 3;
    cx.lane = lane;
    cx.m0 = blockIdx.y * TBM;
    cx.n0 = blockIdx.x * TBN;

    float acc[4][8][4];
    gemm_mainloop(A, Bt, M, N, K, cx, As, Bs, acc);

    #pragma unroll
    for (int nt = 0; nt < 8; nt++) {
        int gc = cx.n0 + cx.wn + nt * 8 + 2 * cx.t;
        float bia0 = bias[gc], bia1 = bias[gc + 1];
        #pragma unroll
        for (int mt = 0; mt < 4; mt++) {
            int r0 = cx.m0 + cx.wm + mt * 16 + cx.g;
            int r1 = r0 + 8;
            if (r0 < M) {
                float2 v = make_float2(acc[mt][nt][0] + bia0, acc[mt][nt][1] + bia1);
                *(float2*)(C + (size_t)r0 * N + gc) = v;
            }
            if (r1 < M) {
                float2 v = make_float2(acc[mt][nt][2] + bia0, acc[mt][nt][3] + bia1);
                *(float2*)(C + (size_t)r1 * N + gc) = v;
            }
        }
    }
}

// ---------------------------------------------------------------------------
// QKV GEMM + bias + fused RoPE + scatter into Q/K/V [b,h,s,64].
// Outputs stored PRE-ROUNDED to tf32 so flash can cp.async raw bits.
// ---------------------------------------------------------------------------
__global__ __launch_bounds__(256, 1)
void gemm_qkv_rope_kernel(const float* __restrict__ A,
                          const float* __restrict__ Bt,
                          const float* __restrict__ bias,
                          float* __restrict__ Q,
                          float* __restrict__ K_,
                          float* __restrict__ V) {
    __shared__ uint32_t As[STAGES][TBM][TSTRIDE];
    __shared__ uint32_t Bs[STAGES][TBN][TSTRIDE];

    const int tid  = threadIdx.x;
    const int lane = tid & 31;
    const int warp = tid >> 5;
    GemmCtx cx;
    cx.wm = (warp & 1) * 64;
    cx.wn = (warp >> 1) * 64;
    cx.g = lane >> 2;
    cx.t = lane & 3;
    cx.lane = lane;
    cx.m0 = blockIdx.y * TBM;
    cx.n0 = blockIdx.x * TBN;

    const int M = B_ * S_;

    float acc[4][8][4];
    gemm_mainloop(A, Bt, M, QKV3_, E_, cx, As, Bs, acc);

    const int sect = cx.n0 / E_;                 // 0=q 1=k 2=v
    float* dst = (sect == 0) ? Q : (sect == 1) ? K_ : V;
    const bool do_rope = (sect < 2);

    #pragma unroll
    for (int nt = 0; nt < 8; nt++) {
        int gc = cx.n0 + cx.wn + nt * 8 + 2 * cx.t;   // global col in [0,2304)
        int ec = gc - sect * E_;                      // col within [0,768)
        int h = ec >> 6;
        int d = ec & 63;                              // even
        float bia0 = bias[gc], bia1 = bias[gc + 1];

        #pragma unroll
        for (int mt = 0; mt < 4; mt++) {
            int r0 = cx.m0 + cx.wm + mt * 16 + cx.g;
            int r1 = r0 + 8;
            #pragma unroll
            for (int half = 0; half < 2; half++) {
                int r = half ? r1 : r0;
                if (r >= M) continue;
                float v0 = acc[mt][nt][half * 2 + 0] + bia0;
                float v1 = acc[mt][nt][half * 2 + 1] + bia1;
                int b = r / S_;
                int s = r - b * S_;
                if (do_rope && s > 0) {
                    int p = s - 1;
                    float cs = g_cos[p * DH_ + d];
                    float sn = g_sin[p * DH_ + d];
                    float n0 = v0 * cs - v1 * sn;
                    float n1 = v1 * cs + v0 * sn;
                    v0 = n0; v1 = n1;
                }
                size_t o = ((size_t)(b * H_ + h) * S_ + s) * DH_ + d;
                *(uint2*)(dst + o) = make_uint2(f2tf32(v0), f2tf32(v1));
            }
        }
    }
}

// ---------------------------------------------------------------------------
// TF32 tensor-core flash attention, cp.async double-buffered K/V.
// K-fragments and Q/P-fragments via ldmatrix. K uses its own fragoff whose
// matrix order is m0=rows0-7@k, m1=rows0-7@k+4, m2=rows8-15@k, m3=rows8-15@k+4
// so s[2p] pairs (m0,m1) and s[2p+1] pairs (m2,m3) -- verified mapping.
// V fragments remain scalar LDS (transposed pattern, conflict-free pad 72).
// ---------------------------------------------------------------------------
#define FQ 64
#define FK 64
#define NKTILES ((S_ + FK - 1) / FK)   // 10
#define NQTILES ((S_ + FQ - 1) / FQ)   // 10
#define PADA 68
#define PADV 72

__global__ __launch_bounds__(128, 2)
void flash_tf32_kernel(const float* __restrict__ Q,
                       const float* __restrict__ K,
                       const float* __restrict__ V,
                       const unsigned char* __restrict__ mask,
                       float* __restrict__ ctx) {
    int qb = blockIdx.x;
    int bh = blockIdx.y;
    int h = bh % H_, b = bh / H_;

    int tid  = threadIdx.x;
    int lane = tid & 31;
    int warp = tid >> 5;
    int g = lane >> 2;
    int t = lane & 3;
    int rm = warp * 16;

    __shared__ uint32_t Ks[2][FK][PADA];
    __shared__ uint32_t Vs[2][FK][PADV];
    __shared__ uint32_t Ps[FQ][PADA];    // Q staging, then P tiles
    __shared__ unsigned char ms[2][FK];

    const size_t bh_base = (size_t)bh * S_ * DH_;
    const int q0 = qb * FQ;

    auto load_tile = [&](int s, int k0) {
        #pragma unroll
        for (int i = 0; i < 8; i++) {
            int idx = tid + i * 128;
            int r = idx >> 4, c4 = idx & 15;
            bool ok = (k0 + r) < S_;
            const float* gk = K + bh_base + (size_t)(k0 + r) * DH_ + c4 * 4;
            const float* gv = V + bh_base + (size_t)(k0 + r) * DH_ + c4 * 4;
            cp16((uint32_t)__cvta_generic_to_shared(&Ks[s][r][c4 * 4]), gk, ok);
            cp16((uint32_t)__cvta_generic_to_shared(&Vs[s][r][c4 * 4]), gv, ok);
        }
        asm volatile("cp.async.commit_group;");
    };

    // ---- Prologue: stage Q (cp.async into Ps) + prefetch tile 0 + mask 0 ----
    #pragma unroll
    for (int i = 0; i < 8; i++) {
        int idx = tid + i * 128;
        int r = idx >> 4, c4 = idx & 15;
        bool ok = (q0 + r) < S_;
        const float* gq = Q + bh_base + (size_t)(q0 + r) * DH_ + c4 * 4;
        cp16((uint32_t)__cvta_generic_to_shared(&Ps[r][c4 * 4]), gq, ok);
    }
    asm volatile("cp.async.commit_group;");
    load_tile(0, 0);
    if (tid < FK)
        ms[0][tid] = (tid < S_) ? mask[b * S_ + tid] : (unsigned char)1;

    asm volatile("cp.async.wait_group 0;");
    __syncthreads();

    // LDSM lane offsets
    const uint32_t a_fragoff =
        ((uint32_t)((lane & 15) * PADA + ((lane >> 4) << 2))) * 4;   // A-like (Q/P)
    const uint32_t k_fragoff =
        ((uint32_t)(((((lane >> 4) << 3) + (lane & 7)) * PADA) +
                    (((lane >> 3) & 1) << 2))) * 4;                  // K pairs
    const uint32_t psb = (uint32_t)__cvta_generic_to_shared(&Ps[0][0]);

    // Q fragments via LDSM (warp-private rows of Ps)
    uint32_t qf[8][4];
    #pragma unroll
    for (int ks = 0; ks < 8; ks++) {
        uint32_t a = psb + (uint32_t)((rm * PADA + ks * 8) * 4) + a_fragoff;
        LDSM_X4(qf[ks][0], qf[ks][1], qf[ks][2], qf[ks][3], a);
    }

    float m_st[2] = {-1e30f, -1e30f};
    float l_st[2] = {0.0f, 0.0f};
    float O[8][4];
    #pragma unroll
    for (int nt = 0; nt < 8; nt++)
        #pragma unroll
        for (int i = 0; i < 4; i++) O[nt][i] = 0.0f;

    for (int kt = 0; kt < NKTILES; kt++) {
        int cur = kt & 1;

        if (kt > 0) {
            asm volatile("cp.async.wait_group 0;");
            __syncthreads();
        }

        if (kt + 1 < NKTILES) {
            int k1 = (kt + 1) * FK;
            load_tile(cur ^ 1, k1);
            if (tid < FK)
                ms[cur ^ 1][tid] = (k1 + tid < S_) ? mask[b * S_ + k1 + tid]
                                                   : (unsigned char)1;
        }

        uint32_t ksb = (uint32_t)__cvta_generic_to_shared(&Ks[cur][0][0]);

        // ---- S = Q K^T (LDSM for K fragments) ----
        float s[8][4];
        #pragma unroll
        for (int nt = 0; nt < 8; nt++)
            #pragma unroll
            for (int i = 0; i < 4; i++) s[nt][i] = 0.0f;

        #pragma unroll
        for (int ks = 0; ks < 8; ks++) {
            int kk = ks * 8;
            #pragma unroll
            for (int p = 0; p < 4; p++) {
                uint32_t bf[4];
                uint32_t a = ksb + (uint32_t)((p * 16 * PADA + kk) * 4) + k_fragoff;
                // m0=rows0-7@kk, m1=rows0-7@kk+4, m2=rows8-15@kk, m3=rows8-15@kk+4
                LDSM_X4(bf[0], bf[1], bf[2], bf[3], a);
                MMA_TF32(s[2 * p], qf[ks], (bf + 0));
                MMA_TF32(s[2 * p + 1], qf[ks], (bf + 2));
            }
        }

        // ---- scale + mask ----
        #pragma unroll
        for (int nt = 0; nt < 8; nt++) {
            int c = nt * 8 + 2 * t;
            bool mk0 = ms[cur][c], mk1 = ms[cur][c + 1];
            s[nt][0] = mk0 ? -1e30f : s[nt][0] * 0.125f;
            s[nt][1] = mk1 ? -1e30f : s[nt][1] * 0.125f;
            s[nt][2] = mk0 ? -1e30f : s[nt][2] * 0.125f;
            s[nt][3] = mk1 ? -1e30f : s[nt][3] * 0.125f;
        }

        // ---- online softmax ----
        float tm0 = -1e30f, tm1 = -1e30f;
        #pragma unroll
        for (int nt = 0; nt < 8; nt++) {
            tm0 = fmaxf(tm0, fmaxf(s[nt][0], s[nt][1]));
            tm1 = fmaxf(tm1, fmaxf(s[nt][2], s[nt][3]));
        }
        tm0 = fmaxf(tm0, __shfl_xor_sync(0xffffffffu, tm0, 1));
        tm0 = fmaxf(tm0, __shfl_xor_sync(0xffffffffu, tm0, 2));
        tm1 = fmaxf(tm1, __shfl_xor_sync(0xffffffffu, tm1, 1));
        tm1 = fmaxf(tm1, __shfl_xor_sync(0xffffffffu, tm1, 2));

        float mn0 = fmaxf(m_st[0], tm0);
        float mn1 = fmaxf(m_st[1], tm1);
        float al0 = __expf(m_st[0] - mn0);
        float al1 = __expf(m_st[1] - mn1);

        float rs0 = 0.0f, rs1 = 0.0f;
        #pragma unroll
        for (int nt = 0; nt < 8; nt++) {
            float p0 = __expf(s[nt][0] - mn0);
            float p1 = __expf(s[nt][1] - mn0);
            float p2 = __expf(s[nt][2] - mn1);
            float p3 = __expf(s[nt][3] - mn1);
            s[nt][0] = p0; s[nt][1] = p1; s[nt][2] = p2; s[nt][3] = p3;
            rs0 += p0 + p1;
            rs1 += p2 + p3;
        }
        rs0 += __shfl_xor_sync(0xffffffffu, rs0, 1);
        rs0 += __shfl_xor_sync(0xffffffffu, rs0, 2);
        rs1 += __shfl_xor_sync(0xffffffffu, rs1, 1);
        rs1 += __shfl_xor_sync(0xffffffffu, rs1, 2);

        l_st[0] = l_st[0] * al0 + rs0;
        l_st[1] = l_st[1] * al1 + rs1;
        m_st[0] = mn0;
        m_st[1] = mn1;

        #pragma unroll
        for (int nt = 0; nt < 8; nt++) {
            O[nt][0] *= al0;
            O[nt][1] *= al0;
            O[nt][2] *= al1;
            O[nt][3] *= al1;
        }

        // ---- store P (tf32) into warp-private rows of Ps ----
        #pragma unroll
        for (int nt = 0; nt < 8; nt++) {
            int c = nt * 8 + 2 * t;
            *(uint2*)&Ps[rm + g][c]     = make_uint2(f2tf32(s[nt][0]), f2tf32(s[nt][1]));
            *(uint2*)&Ps[rm + g + 8][c] = make_uint2(f2tf32(s[nt][2]), f2tf32(s[nt][3]));
        }
        __syncwarp();

        // ---- O += P @ V (LDSM for P fragments) ----
        #pragma unroll
        for (int ks = 0; ks < 8; ks++) {
            int kk = ks * 8;
            uint32_t af[4];
            uint32_t a = psb + (uint32_t)((rm * PADA + kk) * 4) + a_fragoff;
            LDSM_X4(af[0], af[1], af[2], af[3], a);
            #pragma unroll
            for (int nt = 0; nt < 8; nt++) {
                uint32_t bf[2];
                bf[0] = Vs[cur][kk + t][nt * 8 + g];
                bf[1] = Vs[cur][kk + t + 4][nt * 8 + g];
                MMA_TF32(O[nt], af, bf);
            }
        }
    }

    // ---- epilogue: normalize + round to tf32 for the proj GEMM ----
    float inv0 = 1.0f / l_st[0];
    float inv1 = 1.0f / l_st[1];
    int r0 = q0 + rm + g;
    int r1 = r0 + 8;
    #pragma unroll
    for (int nt = 0; nt < 8; nt++) {
        int col = h * DH_ + nt * 8 + 2 * t;
        if (r0 < S_) {
            uint2 v = make_uint2(f2tf32(O[nt][0] * inv0), f2tf32(O[nt][1] * inv0));
            *(uint2*)(ctx + (size_t)(b * S_ + r0) * E_ + col) = v;
        }
        if (r1 < S_) {
            uint2 v = make_uint2(f2tf32(O[nt][2] * inv1), f2tf32(O[nt][3] * inv1));
            *(uint2*)(ctx + (size_t)(b * S_ + r1) * E_ + col) = v;
        }
    }
}

// ---------------------------------------------------------------------------
// Launch
// ---------------------------------------------------------------------------
extern "C" void kernel_launch(void* const* d_in, const int* in_sizes, int n_in,
                              void* d_out, int out_size) {
    const float* x      = (const float*)d_in[0];
    const unsigned char* mask = (const unsigned char*)d_in[1];
    const float* W_qkv  = (const float*)d_in[2];
    const float* b_qkv  = (const float*)d_in[3];
    const float* W_proj = (const float*)d_in[4];
    const float* b_proj = (const float*)d_in[5];
    float* out = (float*)d_out;

    float* ctx; cudaGetSymbolAddress((void**)&ctx, g_ctx);
    float* Qp;  cudaGetSymbolAddress((void**)&Qp, g_q);
    float* Kp;  cudaGetSymbolAddress((void**)&Kp, g_k);
    float* Vp;  cudaGetSymbolAddress((void**)&Vp, g_v);
    float* xr;  cudaGetSymbolAddress((void**)&xr, g_xr);
    float* w1t; cudaGetSymbolAddress((void**)&w1t, g_w1t);
    float* w2t; cudaGetSymbolAddress((void**)&w2t, g_w2t);

    const int M = B_ * S_;   // 18464

    // 0) rope tables + tf32 pre-rounding (x) / round+transpose (weights)
    rope_build_kernel<<<NROT_, DH_>>>();
    {
        int n4x = M * E_ / 4;
        round_tf32_kernel<<<(n4x + 255) / 256, 256>>>(x, xr, n4x);
        round_t_kernel<<<dim3(QKV3_ / 32, E_ / 32), dim3(32, 8)>>>(W_qkv, w1t, E_, QKV3_);
        round_t_kernel<<<dim3(E_ / 32, E_ / 32), dim3(32, 8)>>>(W_proj, w2t, E_, E_);
    }

    // 1) qkv GEMM + bias + rope + scatter into Q/K/V [b,h,s,d] (tf32-rounded)
    {
        dim3 grid(QKV3_ / TBN, (M + TBM - 1) / TBM);
        gemm_qkv_rope_kernel<<<grid, 256>>>(xr, w1t, b_qkv, Qp, Kp, Vp);
    }

    // 2) flash attention (tf32 tensor cores; cp.async pipelined, LDSM frags)
    {
        dim3 grid(NQTILES, BH_);
        flash_tf32_kernel<<<grid, 128>>>(Qp, Kp, Vp, mask, ctx);
    }

    // 3) out = ctx @ W_proj + b_proj  (tf32 tensor cores)
    {
        dim3 grid(E_ / TBN, (M + TBM - 1) / TBM);
        gemm_tf32_kernel<<<grid, 256>>>(ctx, w2t, b_proj, out, M, E_, E_);
    }
}

// round 17
// speedup vs baseline: 1.0685x; 1.0685x over previous
#include <cuda_runtime.h>
#include <cstdint>
#include <cstddef>

// Problem constants
#define B_    32
#define S_    577          // 24*24 + 1
#define E_    768
#define H_    12
#define DH_   64
#define PT_   24
#define QKV3_ 2304         // 3*E
#define NROT_ 576          // S-1 rope positions
#define BH_   (B_ * H_)    // 384

// Scratch (device globals; allocation-free per harness rules)
__device__ float g_ctx[(size_t)B_ * S_ * E_];      // [b*s, h*d] (tf32-rounded)
__device__ float g_q[(size_t)BH_ * S_ * DH_];      // [b,h,s,d] (tf32-rounded)
__device__ float g_k[(size_t)BH_ * S_ * DH_];
__device__ float g_v[(size_t)BH_ * S_ * DH_];
__device__ float g_xr[(size_t)B_ * S_ * E_];       // x rounded to tf32
__device__ float g_w1r[(size_t)E_ * QKV3_];        // W_qkv rounded
__device__ float g_w2r[(size_t)E_ * E_];           // W_proj rounded
__device__ float g_cos[NROT_ * DH_];
__device__ float g_sin[NROT_ * DH_];

// ---------------------------------------------------------------------------
// RoPE table
// ---------------------------------------------------------------------------
__global__ void rope_build_kernel() {
    int p = blockIdx.x;      // 0..575
    int d = threadIdx.x;     // 0..63
    int r = p / PT_, c = p % PT_;
    int tcoord = (d < 32) ? r : c;
    int dd = (d < 32) ? d : d - 32;
    int fi = dd >> 1;        // freq index 0..15
    float inv = powf(10000.0f, -(float)(2 * fi) / 32.0f);
    float ang = (float)tcoord * inv;
    g_cos[p * DH_ + d] = cosf(ang);
    g_sin[p * DH_ + d] = sinf(ang);
}

// ---------------------------------------------------------------------------
// Shared tf32 helpers
// ---------------------------------------------------------------------------
__device__ __forceinline__ uint32_t f2tf32(float x) {
    uint32_t r;
    asm("cvt.rna.tf32.f32 %0, %1;" : "=r"(r) : "f"(x));
    return r;
}

#define MMA_TF32(d, a, b)                                                  \
    asm volatile(                                                          \
        "mma.sync.aligned.m16n8k8.row.col.f32.tf32.tf32.f32 "              \
        "{%0,%1,%2,%3}, {%4,%5,%6,%7}, {%8,%9}, {%0,%1,%2,%3};"            \
        : "+f"(d[0]), "+f"(d[1]), "+f"(d[2]), "+f"(d[3])                   \
        : "r"(a[0]), "r"(a[1]), "r"(a[2]), "r"(a[3]), "r"(b[0]), "r"(b[1]))

__device__ __forceinline__ void cp16(uint32_t dst, const void* src, bool pred) {
    asm volatile("cp.async.cg.shared.global [%0], [%1], 16, %2;"
                 :: "r"(dst), "l"(src), "r"(pred ? 16 : 0));
}

// ---------------------------------------------------------------------------
// Elementwise round-to-tf32 (rna). n4 = element count / 4.
// ---------------------------------------------------------------------------
__global__ void round_tf32_kernel(const float* __restrict__ in,
                                  float* __restrict__ out, int n4) {
    int i = blockIdx.x * blockDim.x + threadIdx.x;
    if (i < n4) {
        float4 v = ((const float4*)in)[i];
        uint4 u = make_uint4(f2tf32(v.x), f2tf32(v.y), f2tf32(v.z), f2tf32(v.w));
        ((uint4*)out)[i] = u;
    }
}

// ---------------------------------------------------------------------------
// TF32 GEMM mainloop. CTA tile 128x256, BK=64, 2-stage cp.async double
// buffer (round-14 configuration; best measured). 8 warps (2m x 4n),
// warp 64x64; 8 k-chunks = 256 MMAs/warp per barrier pair.
// A smem [m][k] pad +8 (stride 72 % 32 = 8 -> frag bank 8g+t bijective);
// B smem [k][n] pad +8 (stride 264 % 32 = 8). Conflict-free fragments.
// ---------------------------------------------------------------------------
#define TBM 128
#define TBN 256
#define TBK 64
#define APAD 8     // A row stride 72
#define BPAD 8     // B row stride 264
#define STAGES 2

struct GemmCtx {
    int wm, wn, g, t, m0, n0;
};

__device__ __forceinline__ void gemm_mainloop(
    const float* __restrict__ A, const float* __restrict__ Bm,
    int M, int N, int K, const GemmCtx& cx,
    uint32_t (*As)[TBM][TBK + APAD], uint32_t (*Bs)[TBK][TBN + BPAD],
    float acc[4][8][4])
{
    const int tid = threadIdx.x;

    auto load_stage = [&](int s, int k0) {
        #pragma unroll
        for (int i = 0; i < 8; i++) {
            int c = tid + i * 256;           // 2048 A chunks (128 rows x 16 quads)
            int row = c >> 4, quad = c & 15;
            int gr = cx.m0 + row;
            uint32_t dst = (uint32_t)__cvta_generic_to_shared(&As[s][row][quad * 4]);
            cp16(dst, A + (size_t)gr * K + k0 + quad * 4, gr < M);
        }
        #pragma unroll
        for (int i = 0; i < 16; i++) {
            int c = tid + i * 256;           // 4096 B chunks (64 rows x 64 quads)
            int row = c >> 6, quad = c & 63;
            uint32_t dst = (uint32_t)__cvta_generic_to_shared(&Bs[s][row][quad * 4]);
            cp16(dst, Bm + (size_t)(k0 + row) * N + cx.n0 + quad * 4, true);
        }
        asm volatile("cp.async.commit_group;");
    };

    #pragma unroll
    for (int mt = 0; mt < 4; mt++)
        #pragma unroll
        for (int nt = 0; nt < 8; nt++)
            #pragma unroll
            for (int i = 0; i < 4; i++) acc[mt][nt][i] = 0.0f;

    const int NKT = K / TBK;   // 12

    load_stage(0, 0);

    for (int kt = 0; kt < NKT; kt++) {
        __syncthreads();     // all warps done with the stage we're about to fill
        if (kt + 1 < NKT) {
            load_stage((kt + 1) & 1, (kt + 1) * TBK);
            asm volatile("cp.async.wait_group 1;");   // group kt complete
        } else {
            asm volatile("cp.async.wait_group 0;");
        }
        __syncthreads();     // stage kt visible to all warps

        int cur = kt & 1;
        #pragma unroll
        for (int ks = 0; ks < 8; ks++) {
            int k = ks * 8;
            uint32_t af[4][4], bf[8][2];
            #pragma unroll
            for (int mt = 0; mt < 4; mt++) {
                int rm = cx.wm + mt * 16;
                af[mt][0] = As[cur][rm + cx.g][k + cx.t];
                af[mt][1] = As[cur][rm + cx.g + 8][k + cx.t];
                af[mt][2] = As[cur][rm + cx.g][k + cx.t + 4];
                af[mt][3] = As[cur][rm + cx.g + 8][k + cx.t + 4];
            }
            #pragma unroll
            for (int nt = 0; nt < 8; nt++) {
                int cn = cx.wn + nt * 8;
                bf[nt][0] = Bs[cur][k + cx.t][cn + cx.g];
                bf[nt][1] = Bs[cur][k + cx.t + 4][cn + cx.g];
            }
            #pragma unroll
            for (int mt = 0; mt < 4; mt++)
                #pragma unroll
                for (int nt = 0; nt < 8; nt++)
                    MMA_TF32(acc[mt][nt], af[mt], bf[nt]);
        }
    }
}

// ---------------------------------------------------------------------------
// Generic tf32 GEMM + bias (used for proj)
// ---------------------------------------------------------------------------
__global__ __launch_bounds__(256, 1)
void gemm_tf32_kernel(const float* __restrict__ A,
                      const float* __restrict__ Bm,
                      const float* __restrict__ bias,
                      float* __restrict__ C,
                      int M, int N, int K) {
    __shared__ uint32_t As[STAGES][TBM][TBK + APAD];
    __shared__ uint32_t Bs[STAGES][TBK][TBN + BPAD];

    const int tid  = threadIdx.x;
    const int lane = tid & 31;
    const int warp = tid >> 5;
    GemmCtx cx;
    cx.wm = (warp & 1) * 64;
    cx.wn = (warp >> 1) * 64;
    cx.g = lane >> 2;
    cx.t = lane & 3;
    cx.m0 = blockIdx.y * TBM;
    cx.n0 = blockIdx.x * TBN;

    float acc[4][8][4];
    gemm_mainloop(A, Bm, M, N, K, cx, As, Bs, acc);

    #pragma unroll
    for (int nt = 0; nt < 8; nt++) {
        int gc = cx.n0 + cx.wn + nt * 8 + 2 * cx.t;
        float bia0 = bias[gc], bia1 = bias[gc + 1];
        #pragma unroll
        for (int mt = 0; mt < 4; mt++) {
            int r0 = cx.m0 + cx.wm + mt * 16 + cx.g;
            int r1 = r0 + 8;
            if (r0 < M) {
                float2 v = make_float2(acc[mt][nt][0] + bia0, acc[mt][nt][1] + bia1);
                *(float2*)(C + (size_t)r0 * N + gc) = v;
            }
            if (r1 < M) {
                float2 v = make_float2(acc[mt][nt][2] + bia0, acc[mt][nt][3] + bia1);
                *(float2*)(C + (size_t)r1 * N + gc) = v;
            }
        }
    }
}

// ---------------------------------------------------------------------------
// QKV GEMM + bias + fused RoPE + scatter into Q/K/V [b,h,s,64].
// Outputs stored PRE-ROUNDED to tf32 so flash can cp.async raw bits.
// ---------------------------------------------------------------------------
__global__ __launch_bounds__(256, 1)
void gemm_qkv_rope_kernel(const float* __restrict__ A,
                          const float* __restrict__ Bm,
                          const float* __restrict__ bias,
                          float* __restrict__ Q,
                          float* __restrict__ K_,
                          float* __restrict__ V) {
    __shared__ uint32_t As[STAGES][TBM][TBK + APAD];
    __shared__ uint32_t Bs[STAGES][TBK][TBN + BPAD];

    const int tid  = threadIdx.x;
    const int lane = tid & 31;
    const int warp = tid >> 5;
    GemmCtx cx;
    cx.wm = (warp & 1) * 64;
    cx.wn = (warp >> 1) * 64;
    cx.g = lane >> 2;
    cx.t = lane & 3;
    cx.m0 = blockIdx.y * TBM;
    cx.n0 = blockIdx.x * TBN;

    const int M = B_ * S_;

    float acc[4][8][4];
    gemm_mainloop(A, Bm, M, QKV3_, E_, cx, As, Bs, acc);

    const int sect = cx.n0 / E_;                 // 0=q 1=k 2=v
    float* dst = (sect == 0) ? Q : (sect == 1) ? K_ : V;
    const bool do_rope = (sect < 2);

    #pragma unroll
    for (int nt = 0; nt < 8; nt++) {
        int gc = cx.n0 + cx.wn + nt * 8 + 2 * cx.t;   // global col in [0,2304)
        int ec = gc - sect * E_;                      // col within [0,768)
        int h = ec >> 6;
        int d = ec & 63;                              // even
        float bia0 = bias[gc], bia1 = bias[gc + 1];

        #pragma unroll
        for (int mt = 0; mt < 4; mt++) {
            int r0 = cx.m0 + cx.wm + mt * 16 + cx.g;
            int r1 = r0 + 8;
            #pragma unroll
            for (int half = 0; half < 2; half++) {
                int r = half ? r1 : r0;
                if (r >= M) continue;
                float v0 = acc[mt][nt][half * 2 + 0] + bia0;
                float v1 = acc[mt][nt][half * 2 + 1] + bia1;
                int b = r / S_;
                int s = r - b * S_;
                if (do_rope && s > 0) {
                    int p = s - 1;
                    float cs = g_cos[p * DH_ + d];
                    float sn = g_sin[p * DH_ + d];
                    float n0 = v0 * cs - v1 * sn;
                    float n1 = v1 * cs + v0 * sn;
                    v0 = n0; v1 = n1;
                }
                size_t o = ((size_t)(b * H_ + h) * S_ + s) * DH_ + d;
                *(uint2*)(dst + o) = make_uint2(f2tf32(v0), f2tf32(v1));
            }
        }
    }
}

// ---------------------------------------------------------------------------
// TF32 tensor-core flash attention with cp.async double-buffered K/V.
// (round-12/14 configuration: FQ=64, 128 threads, 2 CTAs/SM.)
// ---------------------------------------------------------------------------
#define FQ 64
#define FK 64
#define NKTILES ((S_ + FK - 1) / FK)   // 10
#define NQTILES ((S_ + FQ - 1) / FQ)   // 10
#define PADA 68
#define PADV 72

__global__ __launch_bounds__(128, 2)
void flash_tf32_kernel(const float* __restrict__ Q,
                       const float* __restrict__ K,
                       const float* __restrict__ V,
                       const unsigned char* __restrict__ mask,
                       float* __restrict__ ctx) {
    int qb = blockIdx.x;
    int bh = blockIdx.y;
    int h = bh % H_, b = bh / H_;

    int tid  = threadIdx.x;
    int lane = tid & 31;
    int warp = tid >> 5;
    int g = lane >> 2;
    int t = lane & 3;
    int rm = warp * 16;

    __shared__ uint32_t Ks[2][FK][PADA];
    __shared__ uint32_t Vs[2][FK][PADV];
    __shared__ uint32_t Ps[FQ][PADA];    // Q staging, then P tiles
    __shared__ unsigned char ms[2][FK];

    const size_t bh_base = (size_t)bh * S_ * DH_;
    const int q0 = qb * FQ;

    auto load_tile = [&](int s, int k0) {
        #pragma unroll
        for (int i = 0; i < 8; i++) {
            int idx = tid + i * 128;
            int r = idx >> 4, c4 = idx & 15;
            bool ok = (k0 + r) < S_;
            const float* gk = K + bh_base + (size_t)(k0 + r) * DH_ + c4 * 4;
            const float* gv = V + bh_base + (size_t)(k0 + r) * DH_ + c4 * 4;
            cp16((uint32_t)__cvta_generic_to_shared(&Ks[s][r][c4 * 4]), gk, ok);
            cp16((uint32_t)__cvta_generic_to_shared(&Vs[s][r][c4 * 4]), gv, ok);
        }
        asm volatile("cp.async.commit_group;");
    };

    // ---- Prologue: stage Q (cp.async into Ps) + prefetch tile 0 + mask 0 ----
    #pragma unroll
    for (int i = 0; i < 8; i++) {
        int idx = tid + i * 128;
        int r = idx >> 4, c4 = idx & 15;
        bool ok = (q0 + r) < S_;
        const float* gq = Q + bh_base + (size_t)(q0 + r) * DH_ + c4 * 4;
        cp16((uint32_t)__cvta_generic_to_shared(&Ps[r][c4 * 4]), gq, ok);
    }
    asm volatile("cp.async.commit_group;");
    load_tile(0, 0);
    if (tid < FK)
        ms[0][tid] = (tid < S_) ? mask[b * S_ + tid] : (unsigned char)1;

    asm volatile("cp.async.wait_group 0;");
    __syncthreads();

    // Q fragments (warp-private rows of Ps)
    uint32_t qf[8][4];
    #pragma unroll
    for (int ks = 0; ks < 8; ks++) {
        int kk = ks * 8;
        qf[ks][0] = Ps[rm + g][kk + t];
        qf[ks][1] = Ps[rm + g + 8][kk + t];
        qf[ks][2] = Ps[rm + g][kk + t + 4];
        qf[ks][3] = Ps[rm + g + 8][kk + t + 4];
    }

    float m_st[2] = {-1e30f, -1e30f};
    float l_st[2] = {0.0f, 0.0f};
    float O[8][4];
    #pragma unroll
    for (int nt = 0; nt < 8; nt++)
        #pragma unroll
        for (int i = 0; i < 4; i++) O[nt][i] = 0.0f;

    for (int kt = 0; kt < NKTILES; kt++) {
        int cur = kt & 1;

        if (kt > 0) {
            asm volatile("cp.async.wait_group 0;");
            __syncthreads();
        }

        if (kt + 1 < NKTILES) {
            int k1 = (kt + 1) * FK;
            load_tile(cur ^ 1, k1);
            if (tid < FK)
                ms[cur ^ 1][tid] = (k1 + tid < S_) ? mask[b * S_ + k1 + tid]
                                                   : (unsigned char)1;
        }

        // ---- S = Q K^T ----
        float s[8][4];
        #pragma unroll
        for (int nt = 0; nt < 8; nt++)
            #pragma unroll
            for (int i = 0; i < 4; i++) s[nt][i] = 0.0f;

        #pragma unroll
        for (int ks = 0; ks < 8; ks++) {
            int kk = ks * 8;
            #pragma unroll
            for (int nt = 0; nt < 8; nt++) {
                uint32_t bf[2];
                bf[0] = Ks[cur][nt * 8 + g][kk + t];
                bf[1] = Ks[cur][nt * 8 + g][kk + t + 4];
                MMA_TF32(s[nt], qf[ks], bf);
            }
        }

        // ---- scale + mask ----
        #pragma unroll
        for (int nt = 0; nt < 8; nt++) {
            int c = nt * 8 + 2 * t;
            bool mk0 = ms[cur][c], mk1 = ms[cur][c + 1];
            s[nt][0] = mk0 ? -1e30f : s[nt][0] * 0.125f;
            s[nt][1] = mk1 ? -1e30f : s[nt][1] * 0.125f;
            s[nt][2] = mk0 ? -1e30f : s[nt][2] * 0.125f;
            s[nt][3] = mk1 ? -1e30f : s[nt][3] * 0.125f;
        }

        // ---- online softmax ----
        float tm0 = -1e30f, tm1 = -1e30f;
        #pragma unroll
        for (int nt = 0; nt < 8; nt++) {
            tm0 = fmaxf(tm0, fmaxf(s[nt][0], s[nt][1]));
            tm1 = fmaxf(tm1, fmaxf(s[nt][2], s[nt][3]));
        }
        tm0 = fmaxf(tm0, __shfl_xor_sync(0xffffffffu, tm0, 1));
        tm0 = fmaxf(tm0, __shfl_xor_sync(0xffffffffu, tm0, 2));
        tm1 = fmaxf(tm1, __shfl_xor_sync(0xffffffffu, tm1, 1));
        tm1 = fmaxf(tm1, __shfl_xor_sync(0xffffffffu, tm1, 2));

        float mn0 = fmaxf(m_st[0], tm0);
        float mn1 = fmaxf(m_st[1], tm1);
        float al0 = __expf(m_st[0] - mn0);
        float al1 = __expf(m_st[1] - mn1);

        float rs0 = 0.0f, rs1 = 0.0f;
        #pragma unroll
        for (int nt = 0; nt < 8; nt++) {
            float p0 = __expf(s[nt][0] - mn0);
            float p1 = __expf(s[nt][1] - mn0);
            float p2 = __expf(s[nt][2] - mn1);
            float p3 = __expf(s[nt][3] - mn1);
            s[nt][0] = p0; s[nt][1] = p1; s[nt][2] = p2; s[nt][3] = p3;
            rs0 += p0 + p1;
            rs1 += p2 + p3;
        }
        rs0 += __shfl_xor_sync(0xffffffffu, rs0, 1);
        rs0 += __shfl_xor_sync(0xffffffffu, rs0, 2);
        rs1 += __shfl_xor_sync(0xffffffffu, rs1, 1);
        rs1 += __shfl_xor_sync(0xffffffffu, rs1, 2);

        l_st[0] = l_st[0] * al0 + rs0;
        l_st[1] = l_st[1] * al1 + rs1;
        m_st[0] = mn0;
        m_st[1] = mn1;

        #pragma unroll
        for (int nt = 0; nt < 8; nt++) {
            O[nt][0] *= al0;
            O[nt][1] *= al0;
            O[nt][2] *= al1;
            O[nt][3] *= al1;
        }

        // ---- store P (tf32) into warp-private rows of Ps ----
        #pragma unroll
        for (int nt = 0; nt < 8; nt++) {
            int c = nt * 8 + 2 * t;
            *(uint2*)&Ps[rm + g][c]     = make_uint2(f2tf32(s[nt][0]), f2tf32(s[nt][1]));
            *(uint2*)&Ps[rm + g + 8][c] = make_uint2(f2tf32(s[nt][2]), f2tf32(s[nt][3]));
        }
        __syncwarp();

        // ---- O += P @ V ----
        #pragma unroll
        for (int ks = 0; ks < 8; ks++) {
            int kk = ks * 8;
            uint32_t af[4];
            af[0] = Ps[rm + g][kk + t];
            af[1] = Ps[rm + g + 8][kk + t];
            af[2] = Ps[rm + g][kk + t + 4];
            af[3] = Ps[rm + g + 8][kk + t + 4];
            #pragma unroll
            for (int nt = 0; nt < 8; nt++) {
                uint32_t bf[2];
                bf[0] = Vs[cur][kk + t][nt * 8 + g];
                bf[1] = Vs[cur][kk + t + 4][nt * 8 + g];
                MMA_TF32(O[nt], af, bf);
            }
        }
    }

    // ---- epilogue: normalize + round to tf32 for the proj GEMM ----
    float inv0 = 1.0f / l_st[0];
    float inv1 = 1.0f / l_st[1];
    int r0 = q0 + rm + g;
    int r1 = r0 + 8;
    #pragma unroll
    for (int nt = 0; nt < 8; nt++) {
        int col = h * DH_ + nt * 8 + 2 * t;
        if (r0 < S_) {
            uint2 v = make_uint2(f2tf32(O[nt][0] * inv0), f2tf32(O[nt][1] * inv0));
            *(uint2*)(ctx + (size_t)(b * S_ + r0) * E_ + col) = v;
        }
        if (r1 < S_) {
            uint2 v = make_uint2(f2tf32(O[nt][2] * inv1), f2tf32(O[nt][3] * inv1));
            *(uint2*)(ctx + (size_t)(b * S_ + r1) * E_ + col) = v;
        }
    }
}

// ---------------------------------------------------------------------------
// Launch
// ---------------------------------------------------------------------------
extern "C" void kernel_launch(void* const* d_in, const int* in_sizes, int n_in,
                              void* d_out, int out_size) {
    const float* x      = (const float*)d_in[0];
    const unsigned char* mask = (const unsigned char*)d_in[1];
    const float* W_qkv  = (const float*)d_in[2];
    const float* b_qkv  = (const float*)d_in[3];
    const float* W_proj = (const float*)d_in[4];
    const float* b_proj = (const float*)d_in[5];
    float* out = (float*)d_out;

    float* ctx; cudaGetSymbolAddress((void**)&ctx, g_ctx);
    float* Qp;  cudaGetSymbolAddress((void**)&Qp, g_q);
    float* Kp;  cudaGetSymbolAddress((void**)&Kp, g_k);
    float* Vp;  cudaGetSymbolAddress((void**)&Vp, g_v);
    float* xr;  cudaGetSymbolAddress((void**)&xr, g_xr);
    float* w1r; cudaGetSymbolAddress((void**)&w1r, g_w1r);
    float* w2r; cudaGetSymbolAddress((void**)&w2r, g_w2r);

    const int M = B_ * S_;   // 18464

    // 0) rope tables + tf32 pre-rounding of GEMM inputs
    rope_build_kernel<<<NROT_, DH_>>>();
    {
        int n4x = M * E_ / 4;
        round_tf32_kernel<<<(n4x + 255) / 256, 256>>>(x, xr, n4x);
        int n4w1 = E_ * QKV3_ / 4;
        round_tf32_kernel<<<(n4w1 + 255) / 256, 256>>>(W_qkv, w1r, n4w1);
        int n4w2 = E_ * E_ / 4;
        round_tf32_kernel<<<(n4w2 + 255) / 256, 256>>>(W_proj, w2r, n4w2);
    }

    // 1) qkv GEMM + bias + rope + scatter into Q/K/V [b,h,s,d] (tf32-rounded)
    {
        dim3 grid(QKV3_ / TBN, (M + TBM - 1) / TBM);
        gemm_qkv_rope_kernel<<<grid, 256>>>(xr, w1r, b_qkv, Qp, Kp, Vp);
    }

    // 2) flash attention (tf32 tensor cores; cp.async pipelined)
    {
        dim3 grid(NQTILES, BH_);
        flash_tf32_kernel<<<grid, 128>>>(Qp, Kp, Vp, mask, ctx);
    }

    // 3) out = ctx @ W_proj + b_proj  (tf32 tensor cores)
    {
        dim3 grid(E_ / TBN, (M + TBM - 1) / TBM);
        gemm_tf32_kernel<<<grid, 256>>>(ctx, w2r, b_proj, out, M, E_, E_);
    }
}